// round 6
// baseline (speedup 1.0000x reference)
#include <cuda_runtime.h>
#include <math.h>

#define H   256
#define HD  64
#define Bb  2
#define Qq  8
#define Tt  512
#define NQ  128          // number of timestep quads
#define EB  16
#define BT  1024
#define NEGc (-0.6065306597126334f)
#define EPSc 0.00064f

// ---------------- scratch (device globals; no allocations) ----------------
__device__ float g_K  [BT*H];
__device__ float g_Vb [BT*H];
__device__ float g_KK [BT*H];
__device__ float g_sigv[BT*H];
__device__ float g_hA [BT*H];
__device__ float g_Hw1[BT*32];
__device__ float g_qw1[EB*32];
__device__ float g_qA [EB*H];
__device__ float g_rlast[EB*H];
__device__ float g_glast[EB*H];
__device__ float g_o  [EB*H];
// quad-merged scan inputs
__device__ float4 gA [(size_t)EB*NQ*H];  // {kf3, bv3, ew3*kf2, ew3*bv2}
__device__ float4 gB [(size_t)EB*NQ*H];  // {e23*kf1, e23*bv1, e123*kf0, e123*bv0}
__device__ float4 gC [(size_t)EB*NQ*H];  // {E=e0123, C3=e012*kk3, C2=e01*kk2, C1=e0*kk1}
__device__ float4 gD [(size_t)EB*NQ*H];  // {C0=kk0, vv3, vv2, vv1}
__device__ float  gE [(size_t)EB*NQ*H];  // vv0
__device__ float  gq [EB*NQ*4*12];       // 12 per-head scalars per quad

__device__ __forceinline__ float sigmoidf_(float x) { return 1.f / (1.f + __expf(-x)); }

__device__ __forceinline__ float wsum(float v) {
    #pragma unroll
    for (int o = 16; o; o >>= 1) v += __shfl_xor_sync(0xffffffffu, v, o);
    return v;
}

// ---------------- kA: K = Xk@Wk^T, Vb = Xv@Wv^T (Xk/Xv built on the fly) ----------------
__global__ void k_gemm_kv(const float* __restrict__ keyval,
                          const float* __restrict__ x_k, const float* __restrict__ x_v,
                          const float* __restrict__ Wk, const float* __restrict__ Wv) {
    const int z = blockIdx.z;
    const float* __restrict__ xm = z ? x_v : x_k;
    const float* __restrict__ W  = z ? Wv  : Wk;
    float* __restrict__ C = z ? g_Vb : g_K;
    __shared__ float As[64][33];
    __shared__ float Ws[64][33];
    int tid = threadIdx.x;
    int tx = tid & 15, ty = tid >> 4;
    int bm = blockIdx.x * 64, bn = blockIdx.y * 64;
    float acc[4][4] = {};
    #pragma unroll 1
    for (int k0 = 0; k0 < H; k0 += 32) {
        #pragma unroll
        for (int l = tid; l < 64*32; l += 256) {
            int r = l >> 5, c = l & 31;
            int m = bm + r, kg = k0 + c;
            int t = m & (Tt - 1);
            float hs = keyval[m*H + kg];
            float hp = (t > 0) ? keyval[(m-1)*H + kg] : 0.f;
            As[r][c] = fmaf(hp - hs, __ldg(&xm[kg]), hs);
            Ws[r][c] = W[(bn + r)*H + kg];
        }
        __syncthreads();
        #pragma unroll
        for (int kk = 0; kk < 32; kk++) {
            float a_[4], w_[4];
            #pragma unroll
            for (int i = 0; i < 4; i++) { a_[i] = As[ty + 16*i][kk]; w_[i] = Ws[tx + 16*i][kk]; }
            #pragma unroll
            for (int i = 0; i < 4; i++)
                #pragma unroll
                for (int jj = 0; jj < 4; jj++) acc[i][jj] = fmaf(a_[i], w_[jj], acc[i][jj]);
        }
        __syncthreads();
    }
    #pragma unroll
    for (int i = 0; i < 4; i++)
        #pragma unroll
        for (int jj = 0; jj < 4; jj++)
            C[(bm + ty + 16*i)*H + (bn + tx + 16*jj)] = acc[i][jj];
}

// ---------------- kB: fused per-bt small chains + kk-normalize ----------------
__global__ void k_bt(const float* __restrict__ keyval,
                     const float* __restrict__ x_v, const float* __restrict__ x_w,
                     const float* __restrict__ x_a,
                     const float* __restrict__ w1, const float* __restrict__ v1,
                     const float* __restrict__ a1,
                     const float* __restrict__ v2, const float* __restrict__ a2,
                     const float* __restrict__ v0, const float* __restrict__ k_k) {
    int bt = blockIdx.x; int j = threadIdx.x;
    int t = bt & (Tt - 1);
    __shared__ float xv_s[H], xw_s[H], xa_s[H];
    __shared__ float red[3][8][32];
    __shared__ float mid[3][32];
    __shared__ float ws2[8];
    float hs = keyval[bt*H + j];
    float hp = (t > 0) ? keyval[(bt-1)*H + j] : 0.f;
    xv_s[j] = fmaf(hp - hs, x_v[j], hs);
    xw_s[j] = hs * (1.f - x_w[j]);
    xa_s[j] = hs * (1.f - x_a[j]);
    __syncthreads();
    int w = j >> 5, ln = j & 31;
    int kbase = w * 32;
    float pw = 0.f, pv = 0.f, pa = 0.f;
    #pragma unroll
    for (int kk = 0; kk < 32; kk++) {
        int k = kbase + kk;
        pw = fmaf(xw_s[k], w1[k*32 + ln], pw);
        pv = fmaf(xv_s[k], v1[k*32 + ln], pv);
        pa = fmaf(xa_s[k], a1[k*32 + ln], pa);
    }
    red[0][w][ln] = pw; red[1][w][ln] = pv; red[2][w][ln] = pa;
    __syncthreads();
    if (j < 96) {
        int m = j >> 5, d = j & 31;
        float s = 0.f;
        #pragma unroll
        for (int ww = 0; ww < 8; ww++) s += red[m][ww][d];
        mid[m][d] = s;
        if (m == 0) g_Hw1[bt*32 + d] = s;
    }
    __syncthreads();
    float av = 0.f, aa = 0.f;
    #pragma unroll
    for (int d = 0; d < 32; d++) {
        av = fmaf(mid[1][d], v2[d*H + j], av);
        aa = fmaf(mid[2][d], a2[d*H + j], aa);
    }
    g_sigv[bt*H + j] = sigmoidf_(av + v0[j]);
    g_hA[bt*H + j]   = aa;
    float kkv = g_K[bt*H + j] * k_k[j];
    float sq = wsum(kkv * kkv);
    if (ln == 0) ws2[w] = sq;
    __syncthreads();
    int head = j >> 6;
    float nrm = sqrtf(ws2[2*head] + ws2[2*head + 1]);
    g_KK[bt*H + j] = kkv / fmaxf(nrm, 1e-12f);
}

// ---------------- kC: fused per-eb work (qw1, qA, glast, rlast=Xr@Wr^T) ----------------
__global__ void k_q(const float* __restrict__ query, const float* __restrict__ keyval,
                    const float* __restrict__ x_r, const float* __restrict__ x_g,
                    const float* __restrict__ x_w, const float* __restrict__ x_a,
                    const float* __restrict__ w1, const float* __restrict__ a1,
                    const float* __restrict__ g1, const float* __restrict__ a2,
                    const float* __restrict__ g2, const float* __restrict__ Wr) {
    int eb = blockIdx.x; int j = threadIdx.x;
    int b = eb >> 3;
    __shared__ float xr_s[H], xg_s[H], xw_s[H], xa_s[H];
    __shared__ float red[4][8][32];
    __shared__ float ta[32], tg[64];
    float qv  = query[eb*H + j];
    float hsL = keyval[(b*Tt + Tt - 1)*H + j];
    xr_s[j] = fmaf(qv - hsL, x_r[j], hsL);
    xg_s[j] = fmaf(qv - hsL, x_g[j], hsL);
    xw_s[j] = qv * x_w[j];
    xa_s[j] = qv * x_a[j];
    __syncthreads();
    int w = j >> 5, ln = j & 31;
    int kbase = w * 32;
    float pw = 0.f, pa = 0.f, pg0 = 0.f, pg1 = 0.f;
    #pragma unroll
    for (int kk = 0; kk < 32; kk++) {
        int k = kbase + kk;
        pw  = fmaf(xw_s[k], w1[k*32 + ln], pw);
        pa  = fmaf(xa_s[k], a1[k*32 + ln], pa);
        pg0 = fmaf(xg_s[k], g1[k*64 + ln], pg0);
        pg1 = fmaf(xg_s[k], g1[k*64 + 32 + ln], pg1);
    }
    red[0][w][ln] = pw; red[1][w][ln] = pa; red[2][w][ln] = pg0; red[3][w][ln] = pg1;
    __syncthreads();
    if (j < 128) {
        int m = j >> 5, d = j & 31;
        float s = 0.f;
        #pragma unroll
        for (int ww = 0; ww < 8; ww++) s += red[m][ww][d];
        if      (m == 0) g_qw1[eb*32 + d] = s;
        else if (m == 1) ta[d] = s;
        else if (m == 2) tg[d] = sigmoidf_(s);
        else             tg[32 + d] = sigmoidf_(s);
    }
    __syncthreads();
    float aa = 0.f, gg = 0.f;
    #pragma unroll
    for (int d = 0; d < 32; d++) aa = fmaf(ta[d], a2[d*H + j], aa);
    #pragma unroll
    for (int d = 0; d < 64; d++) gg = fmaf(tg[d], g2[d*H + j], gg);
    g_qA[eb*H + j]    = aa;
    g_glast[eb*H + j] = gg;
    float xrp[8];
    #pragma unroll
    for (int m = 0; m < 8; m++) xrp[m] = xr_s[ln*8 + m];
    #pragma unroll 1
    for (int rr = 0; rr < 32; rr++) {
        int n = rr*8 + w;
        const float4* Wrow = (const float4*)(Wr + n*H + ln*8);
        float4 a4 = Wrow[0], b4 = Wrow[1];
        float acc = xrp[0]*a4.x + xrp[1]*a4.y + xrp[2]*a4.z + xrp[3]*a4.w
                  + xrp[4]*b4.x + xrp[5]*b4.y + xrp[6]*b4.z + xrp[7]*b4.w;
        acc = wsum(acc);
        if (ln == 0) g_rlast[eb*H + n] = acc;
    }
}

// ---------------- kD: per-(eb, quad) scan-input precompute ----------------
// quad p covers timesteps t0..t3 = 4p..4p+3 (t3 processed first in backward order)
__global__ void k_quad(const float* __restrict__ v_first, const float* __restrict__ w2,
                       const float* __restrict__ w0, const float* __restrict__ a0,
                       const float* __restrict__ k_a) {
    int p = blockIdx.x, eb = blockIdx.y;
    int b = eb >> 3;
    int t0 = 4*p;
    int j = threadIdx.x;
    __shared__ float th[4][32];
    __shared__ float sq[12][8];
    if (j < 128) {
        int m = j >> 5, d = j & 31;
        th[m][d] = tanhf(g_Hw1[(b*Tt + t0 + m)*32 + d] + g_qw1[eb*32 + d]);
    }
    __syncthreads();
    float ac[4] = {0.f, 0.f, 0.f, 0.f};
    #pragma unroll
    for (int d = 0; d < 32; d++) {
        float wd = w2[d*H + j];
        ac[0] = fmaf(th[0][d], wd, ac[0]);
        ac[1] = fmaf(th[1][d], wd, ac[1]);
        ac[2] = fmaf(th[2][d], wd, ac[2]);
        ac[3] = fmaf(th[3][d], wd, ac[3]);
    }
    float w0j = w0[j], a0j = a0[j], kaj = k_a[j], qAj = g_qA[eb*H + j];
    float ew[4], kf[4], kk[4], bv[4], vv[4];
    #pragma unroll
    for (int i = 0; i < 4; i++) {
        int bt = b*Tt + t0 + i;
        ew[i] = __expf(NEGc * sigmoidf_(w0j + ac[i]));
        float a4 = sigmoidf_(a0j + g_hA[bt*H + j] + qAj);
        kf[i] = g_K[bt*H + j] * fmaf(a4 - 1.f, kaj, 1.f);
        kk[i] = g_KK[bt*H + j];
        bv[i] = kk[i] * a4;
        float vb = g_Vb[bt*H + j], sv = g_sigv[bt*H + j];
        float vf = v_first[((size_t)eb*Tt + t0 + i)*H + j];
        vv[i] = fmaf(vf - vb, sv, vb);
    }
    float e23 = ew[2]*ew[3], e123 = ew[1]*e23, e0123 = ew[0]*e123;
    float e01 = ew[0]*ew[1];
    size_t idx = ((size_t)eb*NQ + p)*H + j;
    gA[idx] = make_float4(kf[3], bv[3], ew[3]*kf[2], ew[3]*bv[2]);
    gB[idx] = make_float4(e23*kf[1], e23*bv[1], e123*kf[0], e123*bv[0]);
    gC[idx] = make_float4(e0123, e01*ew[2]*kk[3], e01*kk[2], ew[0]*kk[1]);
    gD[idx] = make_float4(kk[0], vv[3], vv[2], vv[1]);
    gE[idx] = vv[0];
    // 12 per-head scalars (dot over the 64 head dims)
    float w2kk3  = ew[2]*kk[3];
    float w12kk3 = ew[1]*w2kk3;
    float w1kk2  = ew[1]*kk[2];
    float dd[12];
    dd[0]  = kk[3]*kf[2];  dd[1]  = kk[3]*bv[2];
    dd[2]  = w2kk3*kf[1];  dd[3]  = w2kk3*bv[1];
    dd[4]  = kk[2]*kf[1];  dd[5]  = kk[2]*bv[1];
    dd[6]  = w12kk3*kf[0]; dd[7]  = w12kk3*bv[0];
    dd[8]  = w1kk2*kf[0];  dd[9]  = w1kk2*bv[0];
    dd[10] = kk[1]*kf[0];  dd[11] = kk[1]*bv[0];
    #pragma unroll
    for (int off = 16; off; off >>= 1) {
        #pragma unroll
        for (int s = 0; s < 12; s++) dd[s] += __shfl_xor_sync(0xffffffffu, dd[s], off);
    }
    int w = j >> 5, ln = j & 31;
    if (ln == 0) {
        #pragma unroll
        for (int s = 0; s < 12; s++) sq[s][w] = dd[s];
    }
    __syncthreads();
    if (j < 48) {
        int h = j / 12, s = j % 12;
        gq[((eb*NQ + p)*4 + h)*12 + s] = sq[s][2*h] + sq[s][2*h + 1];
    }
}

// ---------------- kE: backward scan, 1 warp per (eb, head), quad steps ----------------
#define PF 4
__global__ void __launch_bounds__(32) k_scan(const float* __restrict__ r_k,
                       const float* __restrict__ gn_w, const float* __restrict__ gn_b) {
    int wb = blockIdx.x;
    int eb = wb >> 2, h = wb & 3;
    int ln = threadIdx.x;
    int i0 = h*HD + ln, i1 = i0 + 32;
    float u0 = g_rlast[eb*H + i0], u1 = g_rlast[eb*H + i1];
    float o0 = 0.f, o1 = 0.f;
    const float4* __restrict__ pA = gA + (size_t)eb*NQ*H;
    const float4* __restrict__ pB = gB + (size_t)eb*NQ*H;
    const float4* __restrict__ pC = gC + (size_t)eb*NQ*H;
    const float4* __restrict__ pD = gD + (size_t)eb*NQ*H;
    const float*  __restrict__ pE = gE + (size_t)eb*NQ*H;
    const float4* __restrict__ pQ = (const float4*)(gq + (size_t)eb*NQ*4*12) + h*3;

    float4 A0[PF], A1[PF], B0[PF], B1[PF], C0[PF], C1[PF], D0[PF], D1[PF];
    float  E0[PF], E1[PF];
    float4 Q0[2], Q1[2], Q2[2];
    #pragma unroll
    for (int s = 0; s < PF; s++) {
        int p = NQ - 1 - s;
        size_t base = (size_t)p*H;
        A0[s] = pA[base + i0]; A1[s] = pA[base + i1];
        B0[s] = pB[base + i0]; B1[s] = pB[base + i1];
        C0[s] = pC[base + i0]; C1[s] = pC[base + i1];
        D0[s] = pD[base + i0]; D1[s] = pD[base + i1];
        E0[s] = pE[base + i0]; E1[s] = pE[base + i1];
    }
    // FIX: store initial Q at slot (p & 1) so loop's qi = p & 1 matches
    #pragma unroll
    for (int s = 0; s < 2; s++) {
        int p = NQ - 1 - s;
        int slot = p & 1;
        Q0[slot] = pQ[(size_t)p*12];     // {d32k,d32b,d31k,d31b}
        Q1[slot] = pQ[(size_t)p*12 + 1]; // {d21k,d21b,d30k,d30b}
        Q2[slot] = pQ[(size_t)p*12 + 2]; // {d20k,d20b,d10k,d10b}
    }
    #pragma unroll 1
    for (int p0 = NQ - 1; p0 >= PF - 1; p0 -= PF) {
        #pragma unroll
        for (int s = 0; s < PF; s++) {
            int p = p0 - s;
            float4 cA0 = A0[s], cA1 = A1[s], cB0 = B0[s], cB1 = B1[s];
            float4 cC0 = C0[s], cC1 = C1[s], cD0 = D0[s], cD1 = D1[s];
            float  cE0 = E0[s], cE1 = E1[s];
            int qi = p & 1;
            float4 cQ0 = Q0[qi], cQ1 = Q1[qi], cQ2 = Q2[qi];
            // L2 prefetch ~8 quads ahead
            int pl2 = p - 2*PF;
            if (pl2 >= 0) {
                size_t lb = (size_t)pl2*H;
                asm volatile("prefetch.global.L2 [%0];" :: "l"(pA + lb + i0));
                asm volatile("prefetch.global.L2 [%0];" :: "l"(pB + lb + i0));
                asm volatile("prefetch.global.L2 [%0];" :: "l"(pC + lb + i0));
                asm volatile("prefetch.global.L2 [%0];" :: "l"(pD + lb + i0));
                asm volatile("prefetch.global.L2 [%0];" :: "l"(pA + lb + i1));
                asm volatile("prefetch.global.L2 [%0];" :: "l"(pB + lb + i1));
                asm volatile("prefetch.global.L2 [%0];" :: "l"(pC + lb + i1));
                asm volatile("prefetch.global.L2 [%0];" :: "l"(pD + lb + i1));
            }
            // register-ring refill for p-PF
            int pn = p - PF;
            if (pn >= 0) {
                size_t nb = (size_t)pn*H;
                A0[s] = pA[nb + i0]; A1[s] = pA[nb + i1];
                B0[s] = pB[nb + i0]; B1[s] = pB[nb + i1];
                C0[s] = pC[nb + i0]; C1[s] = pC[nb + i1];
                D0[s] = pD[nb + i0]; D1[s] = pD[nb + i1];
                E0[s] = pE[nb + i0]; E1[s] = pE[nb + i1];
            }
            int pq = p - 2;
            if (pq >= 0) {
                Q0[qi] = pQ[(size_t)pq*12];
                Q1[qi] = pQ[(size_t)pq*12 + 1];
                Q2[qi] = pQ[(size_t)pq*12 + 2];
            }
            // 8 independent reductions
            float r3 = fmaf(u0, cA0.x, u1*cA1.x);
            float p3 = fmaf(u0, cA0.y, u1*cA1.y);
            float r2 = fmaf(u0, cA0.z, u1*cA1.z);
            float p2 = fmaf(u0, cA0.w, u1*cA1.w);
            float r1 = fmaf(u0, cB0.x, u1*cB1.x);
            float p1 = fmaf(u0, cB0.y, u1*cB1.y);
            float r0 = fmaf(u0, cB0.z, u1*cB1.z);
            float q0 = fmaf(u0, cB0.w, u1*cB1.w);
            #pragma unroll
            for (int off = 16; off; off >>= 1) {
                r3 += __shfl_xor_sync(0xffffffffu, r3, off);
                p3 += __shfl_xor_sync(0xffffffffu, p3, off);
                r2 += __shfl_xor_sync(0xffffffffu, r2, off);
                p2 += __shfl_xor_sync(0xffffffffu, p2, off);
                r1 += __shfl_xor_sync(0xffffffffu, r1, off);
                p1 += __shfl_xor_sync(0xffffffffu, p1, off);
                r0 += __shfl_xor_sync(0xffffffffu, r0, off);
                q0 += __shfl_xor_sync(0xffffffffu, q0, off);
            }
            // scalar triangular corrections
            float c3 = r3, s3 = p3;
            float c2 = fmaf(-s3, cQ0.x, r2);
            float s2 = fmaf(-s3, cQ0.y, p2);
            float c1 = r1 - s3*cQ0.z - s2*cQ1.x;
            float s1 = p1 - s3*cQ0.w - s2*cQ1.y;
            float c0 = r0 - s3*cQ1.z - s2*cQ2.x - s1*cQ2.z;
            float s0 = q0 - s3*cQ1.w - s2*cQ2.y - s1*cQ2.w;
            // output accumulation
            o0 += c3*cD0.y + c2*cD0.z + c1*cD0.w + c0*cE0;
            o1 += c3*cD1.y + c2*cD1.z + c1*cD1.w + c0*cE1;
            // u update: u = E∘u − s3·C3 − s2·C2 − s1·C1 − s0·C0
            u0 = cC0.x*u0 - s3*cC0.y - s2*cC0.z - s1*cC0.w - s0*cD0.x;
            u1 = cC1.x*u1 - s3*cC1.y - s2*cC1.z - s1*cC1.w - s0*cD1.x;
        }
    }
    // groupnorm over the head's 64 values
    float ms = wsum(o0 + o1);
    float sqs = wsum(fmaf(o0, o0, o1*o1));
    float mean = ms * (1.f/64.f);
    float var  = sqs * (1.f/64.f) - mean*mean;
    float inv  = rsqrtf(var + EPSc);
    float on0 = fmaf((o0 - mean)*inv, gn_w[i0], gn_b[i0]);
    float on1 = fmaf((o1 - mean)*inv, gn_w[i1], gn_b[i1]);
    // residual at t = T-1: kf = gA[last].x, vv = gD[last].y
    size_t lb = (size_t)(NQ-1)*H;
    float4 La0 = pA[lb + i0], La1 = pA[lb + i1];
    float4 Ld0 = pD[lb + i0], Ld1 = pD[lb + i1];
    float r0l = g_rlast[eb*H + i0], r1l = g_rlast[eb*H + i1];
    float rr = wsum(r0l*La0.x*r_k[i0] + r1l*La1.x*r_k[i1]);
    on0 = fmaf(rr, Ld0.y, on0);
    on1 = fmaf(rr, Ld1.y, on1);
    g_o[eb*H + i0] = on0 * g_glast[eb*H + i0];
    g_o[eb*H + i1] = on1 * g_glast[eb*H + i1];
}

// ---------------- kF: out = g_o @ Wo^T ----------------
__global__ void k_out(const float* __restrict__ Wo, float* __restrict__ out) {
    int eb = blockIdx.x; int j = threadIdx.x;
    int w = j >> 5, ln = j & 31;
    __shared__ float os[H];
    os[j] = g_o[eb*H + j];
    __syncthreads();
    float xp[8];
    #pragma unroll
    for (int m = 0; m < 8; m++) xp[m] = os[ln*8 + m];
    #pragma unroll 1
    for (int rr = 0; rr < 32; rr++) {
        int n = rr*8 + w;
        const float4* Wrow = (const float4*)(Wo + n*H + ln*8);
        float4 a4 = Wrow[0], b4 = Wrow[1];
        float acc = xp[0]*a4.x + xp[1]*a4.y + xp[2]*a4.z + xp[3]*a4.w
                  + xp[4]*b4.x + xp[5]*b4.y + xp[6]*b4.z + xp[7]*b4.w;
        acc = wsum(acc);
        if (ln == 0) out[eb*H + n] = acc;
    }
}

// ---------------- launch ----------------
extern "C" void kernel_launch(void* const* d_in, const int* in_sizes, int n_in,
                              void* d_out, int out_size) {
    const float* query   = (const float*)d_in[0];
    const float* keyval  = (const float*)d_in[1];
    const float* v_first = (const float*)d_in[2];
    const float* x_r = (const float*)d_in[3];
    const float* x_w = (const float*)d_in[4];
    const float* x_k = (const float*)d_in[5];
    const float* x_v = (const float*)d_in[6];
    const float* x_a = (const float*)d_in[7];
    const float* x_g = (const float*)d_in[8];
    const float* w0  = (const float*)d_in[9];
    const float* w1  = (const float*)d_in[10];
    const float* w2  = (const float*)d_in[11];
    const float* a0  = (const float*)d_in[12];
    const float* a1  = (const float*)d_in[13];
    const float* a2  = (const float*)d_in[14];
    const float* v0  = (const float*)d_in[15];
    const float* v1  = (const float*)d_in[16];
    const float* v2  = (const float*)d_in[17];
    const float* g1  = (const float*)d_in[18];
    const float* g2  = (const float*)d_in[19];
    const float* k_k = (const float*)d_in[20];
    const float* k_a = (const float*)d_in[21];
    const float* r_k = (const float*)d_in[22];
    const float* Wr  = (const float*)d_in[23];
    const float* Wk  = (const float*)d_in[24];
    const float* Wv  = (const float*)d_in[25];
    const float* Wo  = (const float*)d_in[26];
    const float* gn_w = (const float*)d_in[27];
    const float* gn_b = (const float*)d_in[28];
    float* out = (float*)d_out;

    k_gemm_kv<<<dim3(BT/64, H/64, 2), 256>>>(keyval, x_k, x_v, Wk, Wv);
    k_bt<<<BT, H>>>(keyval, x_v, x_w, x_a, w1, v1, a1, v2, a2, v0, k_k);
    k_q<<<EB, H>>>(query, keyval, x_r, x_g, x_w, x_a, w1, a1, g1, a2, g2, Wr);
    k_quad<<<dim3(NQ, EB), H>>>(v_first, w2, w0, a0, k_a);
    k_scan<<<EB*4, 32>>>(r_k, gn_w, gn_b);
    k_out<<<EB, H>>>(Wo, out);
    (void)in_sizes; (void)n_in; (void)out_size;
}